// round 11
// baseline (speedup 1.0000x reference)
#include <cuda_runtime.h>

// PManifold: B=64, H=2, N=512, K=64, M=16  — fused single kernel, R10.
// output (b,h,k',m) = log0(exp0( sum over a of log0(exp0(point n)+theta_k) ))
// with k = a>>3, n = (a&7)*64 + k' (reference's reshape scramble).
// Collapse: v_m = A0*[m==0] + A1*[m==1] + sum_k F_k*theta_k[m];
// log0(exp0(v)) == min(||v||, atanh(MX))/||v|| * v exactly.
// R10: MUFU 3->2 per eval via atanh(r) = ln(1+r) - 0.5*ln(1-s)  (exact, since
// (1-r)(1+r)=1-s), with ln(1+r)/r by the A&S 4.1.44 degree-8 minimax poly
// (|eps| <= 3e-8 on [0,1]) -> f = P(r) - 0.5*ln2*lg2(1-s)*rsqrt(s).

#define B_ 64
#define H_ 2
#define N_ 512
#define K_ 64
#define M_ 16

#define EPS2_ 1e-14f
// atanh(fp32(1-1e-5)) in double precision (epilogue clip only)
#define ATMX_ 6.1023535f
// 0.5 * ln(2)
#define HALF_LN2_ 0.34657359027997264f

// A&S 4.1.44: ln(1+x) = A1 x + ... + A8 x^8, |eps| <= 3e-8 on [0,1]
#define PA1_  0.9999964239f
#define PA2_ -0.4998741238f
#define PA3_  0.3317990258f
#define PA4_ -0.2407338084f
#define PA5_  0.1676540711f
#define PA6_ -0.0953293897f
#define PA7_  0.0360884937f
#define PA8_ -0.0064535442f

// f = atanh(sqrt(s))/sqrt(s), given s, u=1-s, ri=rsqrt(s)
__device__ __forceinline__ float f_eval(float s, float ri)
{
    float u = 1.0f - s;
    float L = __log2f(u);          // MUFU #2
    float r = s * ri;
    float p = fmaf(PA8_, r, PA7_);
    p = fmaf(p, r, PA6_);
    p = fmaf(p, r, PA5_);
    p = fmaf(p, r, PA4_);
    p = fmaf(p, r, PA3_);
    p = fmaf(p, r, PA2_);
    p = fmaf(p, r, PA1_);          // p = ln(1+r)/r
    float t = L * ri;
    return fmaf(t, -HALF_LN2_, p); // P(r) - 0.5*ln2*lg2(1-s)/r
}

__global__ __launch_bounds__(256, 5) void pm_fused(const float* __restrict__ in,
                                                   const float* __restrict__ theta,
                                                   float* __restrict__ out)
{
    __shared__ float4 e_pts[8][8];        // [r][k'-kbase]: (e0,e1,q,0)
    __shared__ float  th_t[M_][68];       // transposed theta: [m][k], pad 68
    __shared__ float4 tk_s[K_];           // per-k (2*t0, 2*t1, Dk+EPS2, 0)
    __shared__ float  F_sh[8][K_];        // per-warp F_k

    const int bh    = blockIdx.x >> 3;          // b*2 + h
    const int kbase = (blockIdx.x & 7) << 3;    // k' block base
    const int h     = bh & 1;
    const int tid   = threadIdx.x;
    const int w     = tid >> 5;
    const int lane  = tid & 31;

    // ---- prologue: theta staging (transposed) + per-k constants ----
    {
        float4 tv = reinterpret_cast<const float4*>(theta + h * (K_ * M_))[tid];
        int k = tid >> 2, q = tid & 3;            // thread holds theta_k[4q..4q+3]
        th_t[4 * q + 0][k] = tv.x;
        th_t[4 * q + 1][k] = tv.y;
        th_t[4 * q + 2][k] = tv.z;
        th_t[4 * q + 3][k] = tv.w;
        // Dk = sum_m theta_k[m]^2 over the 4 threads of row k (+EPS2 folded)
        float p = fmaf(tv.x, tv.x, fmaf(tv.y, tv.y, fmaf(tv.z, tv.z, tv.w * tv.w)));
        p += __shfl_xor_sync(0xffffffffu, p, 1);
        p += __shfl_xor_sync(0xffffffffu, p, 2);
        if (q == 0) tk_s[k] = make_float4(tv.x + tv.x, tv.y + tv.y, p + EPS2_, 0.0f);
    }

    // ---- prologue: exp0 for this block's 64 points, all 8 warps ----
    if (lane < 8) {
        int idx = w * 8 + lane;                   // 0..63
        int r = idx >> 3, j = idx & 7;
        float2 d = reinterpret_cast<const float2*>(in)[bh * N_ + r * 64 + kbase + j];
        float s   = fmaf(d.x, d.x, fmaf(d.y, d.y, EPS2_));
        float rin = rsqrtf(s);
        float n   = s * rin;                      // ||d||
        float e2  = __expf(n + n);
        float big = (1.0f - __fdividef(2.0f, e2 + 1.0f)) * rin;
        float sml = fmaf(s, fmaf(s, 2.0f / 15.0f, -1.0f / 3.0f), 1.0f);
        float sc  = (s < 1e-3f) ? sml : big;
        e_pts[r][j] = make_float4(d.x * sc, d.y * sc, (sc * sc) * s, 0.0f);
    }
    __syncthreads();

    // ---- main: warp w owns output k' = kbase + w; lane owns theta rows
    //      k = lane and k = lane + 32 ----
    const float4 ca = tk_s[lane];
    const float4 cb = tk_s[lane + 32];

    float Fa = 0.0f, Fb = 0.0f, A0 = 0.0f, A1 = 0.0f;
    #pragma unroll
    for (int r = 0; r < 8; ++r) {
        float4 e = e_pts[r][w];           // warp-broadcast LDS.128
        // s = q + 2 t0 e0 + 2 t1 e1 + (Dk + eps); all terms >= 0, s < 1
        float sA = fmaf(ca.x, e.x, fmaf(ca.y, e.y, e.z)) + ca.z;
        float sB = fmaf(cb.x, e.x, fmaf(cb.y, e.y, e.z)) + cb.z;
        float riA = rsqrtf(sA);           // MUFU #1
        float riB = rsqrtf(sB);
        float fA = f_eval(sA, riA);
        float fB = f_eval(sB, riB);
        Fa += fA;
        Fb += fB;
        float fs = fA + fB;
        A0 = fmaf(fs, e.x, A0);
        A1 = fmaf(fs, e.y, A1);
    }

    // A0/A1 full-warp butterfly (covers all k, all r)
    #pragma unroll
    for (int o = 16; o; o >>= 1) {
        A0 += __shfl_xor_sync(0xffffffffu, A0, o);
        A1 += __shfl_xor_sync(0xffffffffu, A1, o);
    }

    F_sh[w][lane]      = Fa;
    F_sh[w][lane + 32] = Fb;
    __syncwarp();

    // matvec: v_m = sum_k F_k * theta_k[m]; two lanes per m split the k-range
    const int m  = lane & 15;
    const int hk = lane >> 4;
    const float4* t4p = reinterpret_cast<const float4*>(&th_t[m][hk * 32]);
    const float4* f4p = reinterpret_cast<const float4*>(&F_sh[w][hk * 32]);
    float acc = 0.0f;
    #pragma unroll
    for (int j = 0; j < 8; ++j) {
        float4 t4 = t4p[j];
        float4 f4 = f4p[j];
        acc = fmaf(f4.x, t4.x, acc);
        acc = fmaf(f4.y, t4.y, acc);
        acc = fmaf(f4.z, t4.z, acc);
        acc = fmaf(f4.w, t4.w, acc);
    }
    acc += __shfl_xor_sync(0xffffffffu, acc, 16);

    // f is exactly scaled now (no deferred ln2 factor)
    float v = acc;
    if (lane == 0) v += A0;
    if (lane == 1) v += A1;

    // ||v||^2 over the 16 components (butterfly within 16-lane halves)
    float ns2 = fmaf(v, v, EPS2_);
    #pragma unroll
    for (int o = 8; o; o >>= 1) ns2 += __shfl_xor_sync(0xffffffffu, ns2, o);
    float rin   = rsqrtf(ns2);
    float ns    = ns2 * rin;
    float scale = fminf(ns, ATMX_) * rin;   // log0(exp0(v)) scale, exact

    if (lane < 16)
        out[(bh * K_ + kbase + w) * M_ + lane] = scale * v;
}

extern "C" void kernel_launch(void* const* d_in, const int* in_sizes, int n_in,
                              void* d_out, int out_size)
{
    const float* inputs = (const float*)d_in[0];   // (B,H,N,2)
    const float* theta  = (const float*)d_in[1];   // (H,K,M)
    float* out = (float*)d_out;                    // (B,2,K,M)

    pm_fused<<<(B_ * H_ * K_) / 8, 256>>>(inputs, theta, out);
}

// round 12
// speedup vs baseline: 1.0029x; 1.0029x over previous
#include <cuda_runtime.h>

// PManifold: B=64, H=2, N=512, K=64, M=16  — fused single kernel, R11.
// output (b,h,k',m) = log0(exp0( sum over a of log0(exp0(point n)+theta_k) ))
// with k = a>>3, n = (a&7)*64 + k' (reference's reshape scramble).
// Collapse: v_m = A0*[m==0] + A1*[m==1] + sum_k F_k*theta_k[m];
// log0(exp0(v)) == min(||v||, atanh(MX))/||v|| * v exactly.
// R11: each warp computes TWO adjacent outputs SEQUENTIALLY, reusing the
// per-lane theta constants (ca/cb) and sharing one epilogue — amortizes the
// per-warp fixed mass without the register blowup of the parallel-2 variant.

#define B_ 64
#define H_ 2
#define N_ 512
#define K_ 64
#define M_ 16

#define EPS2_ 1e-14f
// atanh(fp32(1-1e-5)) in double precision (epilogue clip only)
#define ATMX_ 6.1023535f
// 0.5 * ln(2)
#define HALF_LN2_ 0.34657359027997264f

__global__ __launch_bounds__(256, 4) void pm_fused(const float* __restrict__ in,
                                                   const float* __restrict__ theta,
                                                   float* __restrict__ out)
{
    __shared__ float4 e_pts[8][16];       // [r][k'-kbase]: (e0,e1,q,0)
    __shared__ float  th_t[M_][68];       // transposed theta: [m][k], pad 68
    __shared__ float4 tk_s[K_];           // per-k (2*t0, 2*t1, Dk+EPS2, 0)
    __shared__ float  F_sh[16][K_];       // [local output][k]

    const int bh    = blockIdx.x >> 2;          // b*2 + h
    const int kbase = (blockIdx.x & 3) << 4;    // 16 outputs per block
    const int h     = bh & 1;
    const int tid   = threadIdx.x;
    const int w     = tid >> 5;
    const int lane  = tid & 31;

    // ---- prologue: theta staging (transposed) + per-k constants ----
    {
        float4 tv = reinterpret_cast<const float4*>(theta + h * (K_ * M_))[tid];
        int k = tid >> 2, q = tid & 3;            // thread holds theta_k[4q..4q+3]
        th_t[4 * q + 0][k] = tv.x;
        th_t[4 * q + 1][k] = tv.y;
        th_t[4 * q + 2][k] = tv.z;
        th_t[4 * q + 3][k] = tv.w;
        // Dk = sum_m theta_k[m]^2 over the 4 threads of row k (+EPS2 folded)
        float p = fmaf(tv.x, tv.x, fmaf(tv.y, tv.y, fmaf(tv.z, tv.z, tv.w * tv.w)));
        p += __shfl_xor_sync(0xffffffffu, p, 1);
        p += __shfl_xor_sync(0xffffffffu, p, 2);
        if (q == 0) tk_s[k] = make_float4(tv.x + tv.x, tv.y + tv.y, p + EPS2_, 0.0f);
    }

    // ---- prologue: exp0 for this block's 128 points ----
    if (tid < 128) {
        int r = tid >> 4, j = tid & 15;
        float2 d = reinterpret_cast<const float2*>(in)[bh * N_ + r * 64 + kbase + j];
        float s   = fmaf(d.x, d.x, fmaf(d.y, d.y, EPS2_));
        float rin = rsqrtf(s);
        float n   = s * rin;                      // ||d||
        float e2  = __expf(n + n);
        float big = (1.0f - __fdividef(2.0f, e2 + 1.0f)) * rin;
        float sml = fmaf(s, fmaf(s, 2.0f / 15.0f, -1.0f / 3.0f), 1.0f);
        float sc  = (s < 1e-3f) ? sml : big;
        e_pts[r][j] = make_float4(d.x * sc, d.y * sc, (sc * sc) * s, 0.0f);
    }
    __syncthreads();

    // ---- main: warp w owns outputs kbase+2w+0 and kbase+2w+1, computed
    //      sequentially; lane owns theta rows k = lane and k = lane + 32 ----
    const float4 ca = tk_s[lane];
    const float4 cb = tk_s[lane + 32];

    float A0s[2], A1s[2];
    #pragma unroll
    for (int oo = 0; oo < 2; ++oo) {
        const int col = 2 * w + oo;
        float Fa = 0.0f, Fb = 0.0f, A0 = 0.0f, A1 = 0.0f;
        #pragma unroll
        for (int r = 0; r < 8; ++r) {
            float4 e = e_pts[r][col];     // warp-broadcast LDS.128
            // s = q + 2 t0 e0 + 2 t1 e1 + (Dk+eps); all terms >= 0, s < 0.956
            float sA = fmaf(ca.x, e.x, fmaf(ca.y, e.y, e.z)) + ca.z;
            float sB = fmaf(cb.x, e.x, fmaf(cb.y, e.y, e.z)) + cb.z;
            float riA = rsqrtf(sA), riB = rsqrtf(sB);   // 1/||x||
            float rA  = sA * riA,   rB  = sB * riB;     // ||x|| (< 0.98)
            // f' = (log2(1+r) - log2(1-r)) / ||x||   (0.5*ln2 deferred)
            float fA = (__log2f(1.0f + rA) - __log2f(1.0f - rA)) * riA;
            float fB = (__log2f(1.0f + rB) - __log2f(1.0f - rB)) * riB;
            Fa += fA;
            Fb += fB;
            float fs = fA + fB;
            A0 = fmaf(fs, e.x, A0);
            A1 = fmaf(fs, e.y, A1);
        }
        #pragma unroll
        for (int o = 16; o; o >>= 1) {
            A0 += __shfl_xor_sync(0xffffffffu, A0, o);
            A1 += __shfl_xor_sync(0xffffffffu, A1, o);
        }
        F_sh[col][lane]      = Fa;
        F_sh[col][lane + 32] = Fb;
        A0s[oo] = A0;                      // warp-uniform after butterfly
        A1s[oo] = A1;
    }
    __syncwarp();

    // matvec: lane owns one (output o, component m); full 64-k dot product
    const int o = lane >> 4;               // 0 -> first output, 1 -> second
    const int m = lane & 15;
    const float4* t4p = reinterpret_cast<const float4*>(&th_t[m][0]);
    const float4* f4p = reinterpret_cast<const float4*>(&F_sh[2 * w + o][0]);
    float acc = 0.0f;
    #pragma unroll
    for (int j = 0; j < 16; ++j) {
        float4 t4 = t4p[j];
        float4 f4 = f4p[j];
        acc = fmaf(f4.x, t4.x, acc);
        acc = fmaf(f4.y, t4.y, acc);
        acc = fmaf(f4.z, t4.z, acc);
        acc = fmaf(f4.w, t4.w, acc);
    }

    float v = acc;
    if (m == 0) v += (o == 0) ? A0s[0] : A0s[1];
    if (m == 1) v += (o == 0) ? A1s[0] : A1s[1];
    v *= HALF_LN2_;

    // ||v||^2 over 16 components (xor offsets stay within each 16-lane half,
    // so one reduction serves both outputs)
    float ns2 = fmaf(v, v, EPS2_);
    #pragma unroll
    for (int off = 8; off; off >>= 1) ns2 += __shfl_xor_sync(0xffffffffu, ns2, off);
    float rin   = rsqrtf(ns2);
    float ns    = ns2 * rin;
    float scale = fminf(ns, ATMX_) * rin;   // log0(exp0(v)) scale, exact

    // coalesced: 32 lanes cover 2 adjacent outputs x 16 components = 128B
    out[(bh * K_ + kbase + 2 * w) * M_ + lane] = scale * v;
}

extern "C" void kernel_launch(void* const* d_in, const int* in_sizes, int n_in,
                              void* d_out, int out_size)
{
    const float* inputs = (const float*)d_in[0];   // (B,H,N,2)
    const float* theta  = (const float*)d_in[1];   // (H,K,M)
    float* out = (float*)d_out;                    // (B,2,K,M)

    pm_fused<<<(B_ * H_ * K_) / 16, 256>>>(inputs, theta, out);
}